// round 8
// baseline (speedup 1.0000x reference)
#include <cuda_runtime.h>

#define N_NODES 50000
#define N_EDGES 800000
#define D 64
#define TR 32            // dst rows per layer block
#define SCAN_B 256
#define SCAN_GRID ((N_NODES + SCAN_B - 1) / SCAN_B)   // 196

typedef unsigned long long ull;

// Scratch (__device__ globals: zero-initialized at load; every kernel restores
// its preconditions so the captured graph replays deterministically)
__device__ int   g_cnt[N_NODES];       // degree counters (zeroed each call by scanC)
__device__ int   g_off[N_NODES];       // CSR exclusive offsets
__device__ int   g_cur[N_NODES];       // fill cursors
__device__ int   g_num[N_NODES];       // degree snapshot
__device__ float g_inv[N_NODES];       // 1/(deg+1)
__device__ int   g_btot[SCAN_GRID];    // per-block totals
__device__ int   g_bbase[SCAN_GRID];   // per-block exclusive bases
__device__ int   g_esrc[N_EDGES];      // CSR column (src) indices
__device__ float g_h1[(size_t)N_NODES * D];
__device__ float g_h2[(size_t)N_NODES * D];

// packed f32x2 fma: d = a*b + d on (lo,hi) pairs (FFMA2, rt_SMSP=1)
__device__ __forceinline__ void ffma2(ull& d, ull a, ull b) {
    asm("fma.rn.f32x2 %0, %1, %2, %0;" : "+l"(d) : "l"(a), "l"(b));
}

// ---------------------------------------------------------------------------
// 1) count in-degrees
__global__ void count_kernel(const int* __restrict__ dst) {
    int e = blockIdx.x * blockDim.x + threadIdx.x;
    if (e < N_EDGES) atomicAdd(&g_cnt[dst[e]], 1);
}

// 2a) per-block scan: local exclusive prefix -> g_off, block total -> g_btot
__global__ void __launch_bounds__(SCAN_B) scanA_kernel() {
    __shared__ int ps[SCAN_B];
    int t = threadIdx.x;
    int n = blockIdx.x * SCAN_B + t;
    int c = (n < N_NODES) ? g_cnt[n] : 0;
    ps[t] = c;
    __syncthreads();
#pragma unroll
    for (int off = 1; off < SCAN_B; off <<= 1) {
        int v = (t >= off) ? ps[t - off] : 0;
        __syncthreads();
        ps[t] += v;
        __syncthreads();
    }
    if (n < N_NODES) {
        g_off[n] = ps[t] - c;          // local exclusive
        g_num[n] = c;
    }
    if (t == SCAN_B - 1) g_btot[blockIdx.x] = ps[t];
}

// 2b) scan of block totals (tiny, one block)
__global__ void __launch_bounds__(SCAN_B) scanB_kernel() {
    __shared__ int ps[SCAN_B];
    int t = threadIdx.x;
    int c = (t < SCAN_GRID) ? g_btot[t] : 0;
    ps[t] = c;
    __syncthreads();
#pragma unroll
    for (int off = 1; off < SCAN_B; off <<= 1) {
        int v = (t >= off) ? ps[t - off] : 0;
        __syncthreads();
        ps[t] += v;
        __syncthreads();
    }
    if (t < SCAN_GRID) g_bbase[t] = ps[t] - c;
}

// 2c) finalize: global offsets, cursors, inv; zero counters for next replay
__global__ void __launch_bounds__(SCAN_B) scanC_kernel() {
    int t = threadIdx.x;
    int n = blockIdx.x * SCAN_B + t;
    if (n < N_NODES) {
        int off = g_off[n] + g_bbase[blockIdx.x];
        g_off[n] = off;
        g_cur[n] = off;
        g_inv[n] = 1.0f / (float)(g_num[n] + 1);
        g_cnt[n] = 0;                  // ready for next replay
    }
}

// 3) bucket-fill CSR column indices
__global__ void fill_kernel(const int* __restrict__ src,
                            const int* __restrict__ dst) {
    int e = blockIdx.x * blockDim.x + threadIdx.x;
    if (e < N_EDGES) {
        int pos = atomicAdd(&g_cur[dst[e]], 1);
        g_esrc[pos] = src[e];
    }
}

// ---------------------------------------------------------------------------
// Fused layer. Gather: warp owns 4 dst rows; for each row, lane L fetches
// index esrc[j+L] (coalesced), shfl broadcasts each index, warp issues up to
// 32 independent 256B row reads (lane covers dims {2L,2L+1}) -> MLP ~deg.
// Then normalize into smem and run FFMA2 register-blocked GEMM + bias(+relu).
template <bool RELU>
__global__ void __launch_bounds__(256) layer_kernel(
        const float* __restrict__ h,
        const float* __restrict__ W,
        const float* __restrict__ b,
        float* __restrict__ out) {
    __shared__ float2 Wq[D * 33];        // Wq[c*33+k2] = (W[2k2][c], W[2k2+1][c])
    __shared__ float vsm[TR * D];
    __shared__ float bs[D];

    int tid = threadIdx.x;
    int rowBase = blockIdx.x * TR;

    float* Wqf = reinterpret_cast<float*>(Wq);
    for (int i = tid; i < D * D; i += 256) {
        int k = i >> 6, c = i & 63;
        Wqf[c * 66 + k] = W[i];
    }
    if (tid < D) bs[tid] = b[tid];

    int warp = tid >> 5;
    int lane = tid & 31;
    int r0 = warp * 4;

    // ---- gather + normalize into vsm ----
    const float2* h2p = reinterpret_cast<const float2*>(h);
#pragma unroll 1
    for (int r = 0; r < 4; r++) {
        int n = rowBase + r0 + r;
        if (n >= N_NODES) break;
        int beg = __ldg(g_off + n);
        int num = __ldg(g_num + n);
        float2 acc = __ldg(h2p + (size_t)n * 32 + lane);   // self row
        int end = beg + num;
#pragma unroll 1
        for (int j = beg; j < end; j += 32) {
            int cnt = end - j;
            if (cnt > 32) cnt = 32;
            int myIdx = (lane < cnt) ? __ldg(g_esrc + j + lane) : 0;
#pragma unroll 1
            for (int e = 0; e < cnt; e++) {
                int s = __shfl_sync(0xffffffffu, myIdx, e);
                float2 a = __ldg(h2p + (size_t)s * 32 + lane);
                acc.x += a.x;
                acc.y += a.y;
            }
        }
        float iv = __ldg(g_inv + n);
        acc.x *= iv;
        acc.y *= iv;
        *reinterpret_cast<float2*>(vsm + (r0 + r) * D + 2 * lane) = acc;
    }
    __syncthreads();

    // ---- FFMA2 GEMM: out[rows, :] = vsm @ W + b ----
    ull acc_a[4], acc_b[4];
#pragma unroll
    for (int r = 0; r < 4; r++) { acc_a[r] = 0ull; acc_b[r] = 0ull; }

    const ull* Wa = reinterpret_cast<const ull*>(Wq) + lane * 33;
    const ull* Wb = reinterpret_cast<const ull*>(Wq) + (lane + 32) * 33;
    const ull* vbase = reinterpret_cast<const ull*>(vsm) + r0 * (D / 2);

#pragma unroll
    for (int k2 = 0; k2 < D / 2; k2++) {
        ull wa = Wa[k2];
        ull wb = Wb[k2];
#pragma unroll
        for (int r = 0; r < 4; r++) {
            ull vp = vbase[r * (D / 2) + k2];
            ffma2(acc_a[r], vp, wa);
            ffma2(acc_b[r], vp, wb);
        }
    }

    float bias0 = bs[lane], bias1 = bs[lane + 32];
#pragma unroll
    for (int r = 0; r < 4; r++) {
        int row = rowBase + r0 + r;
        if (row < N_NODES) {
            float2 pa = *reinterpret_cast<float2*>(&acc_a[r]);
            float2 pb = *reinterpret_cast<float2*>(&acc_b[r]);
            float o0 = pa.x + pa.y + bias0;
            float o1 = pb.x + pb.y + bias1;
            if (RELU) { o0 = fmaxf(o0, 0.f); o1 = fmaxf(o1, 0.f); }
            out[(size_t)row * D + lane]      = o0;
            out[(size_t)row * D + lane + 32] = o1;
        }
    }
}

// ---------------------------------------------------------------------------
extern "C" void kernel_launch(void* const* d_in, const int* in_sizes, int n_in,
                              void* d_out, int out_size) {
    const float* x   = (const float*)d_in[0];
    const int*   src = (const int*)  d_in[1];
    const int*   dst = (const int*)  d_in[2];
    const float* W0  = (const float*)d_in[3];
    const float* b0  = (const float*)d_in[4];
    const float* W1  = (const float*)d_in[5];
    const float* b1  = (const float*)d_in[6];
    const float* W2  = (const float*)d_in[7];
    const float* b2  = (const float*)d_in[8];
    float* out = (float*)d_out;

    float* h1;  cudaGetSymbolAddress((void**)&h1, g_h1);
    float* h2;  cudaGetSymbolAddress((void**)&h2, g_h2);

    const int edge_grid  = (N_EDGES + 255) / 256;
    const int layer_grid = (N_NODES + TR - 1) / TR;   // 1563

    // CSR build (full-chip 3-phase scan)
    count_kernel<<<edge_grid, 256>>>(dst);
    scanA_kernel<<<SCAN_GRID, SCAN_B>>>();
    scanB_kernel<<<1, SCAN_B>>>();
    scanC_kernel<<<SCAN_GRID, SCAN_B>>>();
    fill_kernel<<<edge_grid, 256>>>(src, dst);

    layer_kernel<true ><<<layer_grid, 256>>>(x,  W0, b0, h1);
    layer_kernel<true ><<<layer_grid, 256>>>(h1, W1, b1, h2);
    layer_kernel<false><<<layer_grid, 256>>>(h2, W2, b2, out);
}

// round 9
// speedup vs baseline: 1.4148x; 1.4148x over previous
#include <cuda_runtime.h>

#define N_NODES 50000
#define N_EDGES 800000
#define D 64
#define TR 64            // dst rows per layer block
#define SCAN_B 256
#define SCAN_GRID ((N_NODES + SCAN_B - 1) / SCAN_B)   // 196

typedef unsigned long long ull;

// Scratch (__device__ globals: zero-initialized at load; every kernel restores
// its preconditions so the captured graph replays deterministically)
__device__ int   g_cnt[N_NODES];       // degree counters (zeroed each call by scanC)
__device__ int   g_off[N_NODES];       // CSR exclusive offsets
__device__ int   g_cur[N_NODES];       // fill cursors
__device__ int   g_num[N_NODES];       // degree snapshot
__device__ float g_inv[N_NODES];       // 1/(deg+1)
__device__ int   g_btot[SCAN_GRID];    // per-block totals
__device__ int   g_bbase[SCAN_GRID];   // per-block exclusive bases
__device__ int   g_esrc[N_EDGES];      // CSR column (src) indices
__device__ float g_h1[(size_t)N_NODES * D];
__device__ float g_h2[(size_t)N_NODES * D];

// packed f32x2 fma: d = a*b + d on (lo,hi) pairs (FFMA2, rt_SMSP=1)
__device__ __forceinline__ void ffma2(ull& d, ull a, ull b) {
    asm("fma.rn.f32x2 %0, %1, %2, %0;" : "+l"(d) : "l"(a), "l"(b));
}

// ---------------------------------------------------------------------------
// 1) count in-degrees
__global__ void count_kernel(const int* __restrict__ dst) {
    int e = blockIdx.x * blockDim.x + threadIdx.x;
    if (e < N_EDGES) atomicAdd(&g_cnt[dst[e]], 1);
}

// 2a) per-block scan: local exclusive prefix -> g_off, block total -> g_btot
__global__ void __launch_bounds__(SCAN_B) scanA_kernel() {
    __shared__ int ps[SCAN_B];
    int t = threadIdx.x;
    int n = blockIdx.x * SCAN_B + t;
    int c = (n < N_NODES) ? g_cnt[n] : 0;
    ps[t] = c;
    __syncthreads();
#pragma unroll
    for (int off = 1; off < SCAN_B; off <<= 1) {
        int v = (t >= off) ? ps[t - off] : 0;
        __syncthreads();
        ps[t] += v;
        __syncthreads();
    }
    if (n < N_NODES) {
        g_off[n] = ps[t] - c;          // local exclusive
        g_num[n] = c;
    }
    if (t == SCAN_B - 1) g_btot[blockIdx.x] = ps[t];
}

// 2b) scan of block totals (tiny, one block)
__global__ void __launch_bounds__(SCAN_B) scanB_kernel() {
    __shared__ int ps[SCAN_B];
    int t = threadIdx.x;
    int c = (t < SCAN_GRID) ? g_btot[t] : 0;
    ps[t] = c;
    __syncthreads();
#pragma unroll
    for (int off = 1; off < SCAN_B; off <<= 1) {
        int v = (t >= off) ? ps[t - off] : 0;
        __syncthreads();
        ps[t] += v;
        __syncthreads();
    }
    if (t < SCAN_GRID) g_bbase[t] = ps[t] - c;
}

// 2c) finalize: global offsets, cursors, inv; zero counters for next replay
__global__ void __launch_bounds__(SCAN_B) scanC_kernel() {
    int t = threadIdx.x;
    int n = blockIdx.x * SCAN_B + t;
    if (n < N_NODES) {
        int off = g_off[n] + g_bbase[blockIdx.x];
        g_off[n] = off;
        g_cur[n] = off;
        g_inv[n] = 1.0f / (float)(g_num[n] + 1);
        g_cnt[n] = 0;                  // ready for next replay
    }
}

// 3) bucket-fill CSR column indices
__global__ void fill_kernel(const int* __restrict__ src,
                            const int* __restrict__ dst) {
    int e = blockIdx.x * blockDim.x + threadIdx.x;
    if (e < N_EDGES) {
        int pos = atomicAdd(&g_cur[dst[e]], 1);
        g_esrc[pos] = src[e];
    }
}

// ---------------------------------------------------------------------------
// Fused layer. Gather: warp owns 8 dst rows. Lane covers a quarter-row via
// float4; half-warp 0 (lanes 0-15) processes even edges, half-warp 1 odd edges
// -> one LDG.128 per 2 edges, 4 independent 512B row loads in flight per
// 8-edge chunk. Halves merged once per row via shfl_xor(16). No SHFL on the
// per-edge path. Then FFMA2 register-blocked GEMM + bias(+relu).
template <bool RELU>
__global__ void __launch_bounds__(256) layer_kernel(
        const float* __restrict__ h,
        const float* __restrict__ W,
        const float* __restrict__ b,
        float* __restrict__ out) {
    __shared__ float2 Wq[D * 33];        // Wq[c*33+k2] = (W[2k2][c], W[2k2+1][c])
    __shared__ float vsm[TR * D];
    __shared__ float bs[D];

    int tid = threadIdx.x;
    int rowBase = blockIdx.x * TR;

    float* Wqf = reinterpret_cast<float*>(Wq);
    for (int i = tid; i < D * D; i += 256) {
        int k = i >> 6, c = i & 63;
        Wqf[c * 66 + k] = W[i];
    }
    if (tid < D) bs[tid] = b[tid];

    int warp = tid >> 5;
    int lane = tid & 31;
    int r0 = warp * 8;
    int hw = lane >> 4;      // which half-warp (edge parity)
    int hl = lane & 15;      // quarter-row slot (dims 4*hl .. 4*hl+3)

    // ---- gather + normalize into vsm ----
    const float4* h4 = reinterpret_cast<const float4*>(h);
#pragma unroll 1
    for (int r = 0; r < 8; r++) {
        int n = rowBase + r0 + r;
        if (n >= N_NODES) break;
        int beg = __ldg(g_off + n);
        int num = __ldg(g_num + n);
        float4 acc = make_float4(0.f, 0.f, 0.f, 0.f);
        if (lane < 16) acc = __ldg(h4 + (size_t)n * 16 + hl);   // self row
        int j = beg, end = beg + num;
#pragma unroll 1
        for (; j + 8 <= end; j += 8) {
            int i0 = __ldg(g_esrc + j     + hw);
            int i1 = __ldg(g_esrc + j + 2 + hw);
            int i2 = __ldg(g_esrc + j + 4 + hw);
            int i3 = __ldg(g_esrc + j + 6 + hw);
            float4 a0 = __ldg(h4 + (size_t)i0 * 16 + hl);
            float4 a1 = __ldg(h4 + (size_t)i1 * 16 + hl);
            float4 a2 = __ldg(h4 + (size_t)i2 * 16 + hl);
            float4 a3 = __ldg(h4 + (size_t)i3 * 16 + hl);
            acc.x += (a0.x + a1.x) + (a2.x + a3.x);
            acc.y += (a0.y + a1.y) + (a2.y + a3.y);
            acc.z += (a0.z + a1.z) + (a2.z + a3.z);
            acc.w += (a0.w + a1.w) + (a2.w + a3.w);
        }
        for (; j + 2 <= end; j += 2) {
            int s = __ldg(g_esrc + j + hw);
            float4 a = __ldg(h4 + (size_t)s * 16 + hl);
            acc.x += a.x; acc.y += a.y; acc.z += a.z; acc.w += a.w;
        }
        if (j < end && lane < 16) {
            int s = __ldg(g_esrc + j);
            float4 a = __ldg(h4 + (size_t)s * 16 + hl);
            acc.x += a.x; acc.y += a.y; acc.z += a.z; acc.w += a.w;
        }
        // merge the two edge-parity halves (off the per-edge critical path)
        acc.x += __shfl_xor_sync(0xffffffffu, acc.x, 16);
        acc.y += __shfl_xor_sync(0xffffffffu, acc.y, 16);
        acc.z += __shfl_xor_sync(0xffffffffu, acc.z, 16);
        acc.w += __shfl_xor_sync(0xffffffffu, acc.w, 16);
        float iv = __ldg(g_inv + n);
        if (lane < 16) {
            acc.x *= iv; acc.y *= iv; acc.z *= iv; acc.w *= iv;
            *reinterpret_cast<float4*>(vsm + (r0 + r) * D + 4 * hl) = acc;
        }
    }
    __syncthreads();

    // ---- FFMA2 GEMM: out[rows, :] = vsm @ W + b ----
    ull acc_a[8], acc_b[8];
#pragma unroll
    for (int r = 0; r < 8; r++) { acc_a[r] = 0ull; acc_b[r] = 0ull; }

    const ull* Wa = reinterpret_cast<const ull*>(Wq) + lane * 33;
    const ull* Wb = reinterpret_cast<const ull*>(Wq) + (lane + 32) * 33;
    const ull* vbase = reinterpret_cast<const ull*>(vsm) + r0 * (D / 2);

#pragma unroll
    for (int k2 = 0; k2 < D / 2; k2++) {
        ull wa = Wa[k2];
        ull wb = Wb[k2];
#pragma unroll
        for (int r = 0; r < 8; r++) {
            ull vp = vbase[r * (D / 2) + k2];
            ffma2(acc_a[r], vp, wa);
            ffma2(acc_b[r], vp, wb);
        }
    }

    float bias0 = bs[lane], bias1 = bs[lane + 32];
#pragma unroll
    for (int r = 0; r < 8; r++) {
        int row = rowBase + r0 + r;
        if (row < N_NODES) {
            float2 pa = *reinterpret_cast<float2*>(&acc_a[r]);
            float2 pb = *reinterpret_cast<float2*>(&acc_b[r]);
            float o0 = pa.x + pa.y + bias0;
            float o1 = pb.x + pb.y + bias1;
            if (RELU) { o0 = fmaxf(o0, 0.f); o1 = fmaxf(o1, 0.f); }
            out[(size_t)row * D + lane]      = o0;
            out[(size_t)row * D + lane + 32] = o1;
        }
    }
}

// ---------------------------------------------------------------------------
extern "C" void kernel_launch(void* const* d_in, const int* in_sizes, int n_in,
                              void* d_out, int out_size) {
    const float* x   = (const float*)d_in[0];
    const int*   src = (const int*)  d_in[1];
    const int*   dst = (const int*)  d_in[2];
    const float* W0  = (const float*)d_in[3];
    const float* b0  = (const float*)d_in[4];
    const float* W1  = (const float*)d_in[5];
    const float* b1  = (const float*)d_in[6];
    const float* W2  = (const float*)d_in[7];
    const float* b2  = (const float*)d_in[8];
    float* out = (float*)d_out;

    float* h1;  cudaGetSymbolAddress((void**)&h1, g_h1);
    float* h2;  cudaGetSymbolAddress((void**)&h2, g_h2);

    const int edge_grid  = (N_EDGES + 255) / 256;
    const int layer_grid = (N_NODES + TR - 1) / TR;   // 782

    // CSR build (full-chip 3-phase scan)
    count_kernel<<<edge_grid, 256>>>(dst);
    scanA_kernel<<<SCAN_GRID, SCAN_B>>>();
    scanB_kernel<<<1, SCAN_B>>>();
    scanC_kernel<<<SCAN_GRID, SCAN_B>>>();
    fill_kernel<<<edge_grid, 256>>>(src, dst);

    layer_kernel<true ><<<layer_grid, 256>>>(x,  W0, b0, h1);
    layer_kernel<true ><<<layer_grid, 256>>>(h1, W1, b1, h2);
    layer_kernel<false><<<layer_grid, 256>>>(h2, W2, b2, out);
}

// round 11
// speedup vs baseline: 1.4716x; 1.0401x over previous
#include <cuda_runtime.h>
#include <cuda_fp16.h>

#define N_NODES 50000
#define N_EDGES 800000
#define D 64
#define TR 64            // dst rows per layer block
#define SCAN_B 256
#define SCAN_GRID ((N_NODES + SCAN_B - 1) / SCAN_B)   // 196

typedef unsigned long long ull;

// Scratch (__device__ globals: zero-initialized at load; every kernel restores
// its preconditions so the captured graph replays deterministically)
__device__ int    g_cnt[N_NODES];      // degree counters (zeroed each call by scanC)
__device__ int    g_off[N_NODES];      // CSR exclusive offsets
__device__ int    g_cur[N_NODES];      // fill cursors
__device__ int    g_num[N_NODES];      // degree snapshot
__device__ float  g_inv[N_NODES];      // 1/(deg+1)
__device__ int    g_btot[SCAN_GRID];   // per-block totals
__device__ int    g_bbase[SCAN_GRID];  // per-block exclusive bases
__device__ int    g_esrc[N_EDGES];     // CSR column (src) indices
__device__ __half2 g_hx[(size_t)N_NODES * D / 2];   // fp16 copy of x
__device__ __half2 g_h1[(size_t)N_NODES * D / 2];   // fp16 intermediate h1
__device__ __half2 g_h2[(size_t)N_NODES * D / 2];   // fp16 intermediate h2

// packed f32x2 fma: d = a*b + d on (lo,hi) pairs (FFMA2, rt_SMSP=1)
__device__ __forceinline__ void ffma2(ull& d, ull a, ull b) {
    asm("fma.rn.f32x2 %0, %1, %2, %0;" : "+l"(d) : "l"(a), "l"(b));
}

// ---------------------------------------------------------------------------
// 0) convert x to fp16 once per call
__global__ void cvt_kernel(const float* __restrict__ x) {
    int i = blockIdx.x * blockDim.x + threadIdx.x;   // over N*D/2 half2s
    if (i < N_NODES * (D / 2)) {
        float2 v = __ldg(reinterpret_cast<const float2*>(x) + i);
        g_hx[i] = __floats2half2_rn(v.x, v.y);
    }
}

// 1) count in-degrees
__global__ void count_kernel(const int* __restrict__ dst) {
    int e = blockIdx.x * blockDim.x + threadIdx.x;
    if (e < N_EDGES) atomicAdd(&g_cnt[dst[e]], 1);
}

// 2a) per-block scan: local exclusive prefix -> g_off, block total -> g_btot
__global__ void __launch_bounds__(SCAN_B) scanA_kernel() {
    __shared__ int ps[SCAN_B];
    int t = threadIdx.x;
    int n = blockIdx.x * SCAN_B + t;
    int c = (n < N_NODES) ? g_cnt[n] : 0;
    ps[t] = c;
    __syncthreads();
#pragma unroll
    for (int off = 1; off < SCAN_B; off <<= 1) {
        int v = (t >= off) ? ps[t - off] : 0;
        __syncthreads();
        ps[t] += v;
        __syncthreads();
    }
    if (n < N_NODES) {
        g_off[n] = ps[t] - c;          // local exclusive
        g_num[n] = c;
    }
    if (t == SCAN_B - 1) g_btot[blockIdx.x] = ps[t];
}

// 2b) scan of block totals (tiny, one block)
__global__ void __launch_bounds__(SCAN_B) scanB_kernel() {
    __shared__ int ps[SCAN_B];
    int t = threadIdx.x;
    int c = (t < SCAN_GRID) ? g_btot[t] : 0;
    ps[t] = c;
    __syncthreads();
#pragma unroll
    for (int off = 1; off < SCAN_B; off <<= 1) {
        int v = (t >= off) ? ps[t - off] : 0;
        __syncthreads();
        ps[t] += v;
        __syncthreads();
    }
    if (t < SCAN_GRID) g_bbase[t] = ps[t] - c;
}

// 2c) finalize: global offsets, cursors, inv; zero counters for next replay
__global__ void __launch_bounds__(SCAN_B) scanC_kernel() {
    int t = threadIdx.x;
    int n = blockIdx.x * SCAN_B + t;
    if (n < N_NODES) {
        int off = g_off[n] + g_bbase[blockIdx.x];
        g_off[n] = off;
        g_cur[n] = off;
        g_inv[n] = 1.0f / (float)(g_num[n] + 1);
        g_cnt[n] = 0;                  // ready for next replay
    }
}

// 3) bucket-fill CSR column indices
__global__ void fill_kernel(const int* __restrict__ src,
                            const int* __restrict__ dst) {
    int e = blockIdx.x * blockDim.x + threadIdx.x;
    if (e < N_EDGES) {
        int pos = atomicAdd(&g_cur[dst[e]], 1);
        g_esrc[pos] = src[e];
    }
}

// ---------------------------------------------------------------------------
// Fused layer, fp16 features. Warp owns 8 dst rows. fp16 row = 128B, so one
// warp-wide LDG.128 serves 4 edges: lane group qw=lane>>3 takes edge j+qw,
// slot hl=lane&7 covers dims 8hl..8hl+7 (16B of halves). Accumulate fp32,
// merge the 4 edge groups via shfl_xor(8,16) once per row, normalize, stage
// into fp32 vsm, then FFMA2 GEMM (LDS.128 operands) + bias(+relu). Output is
// fp16 (intermediate layers) or fp32 (final).
__device__ __forceinline__ void acc_half8(float* acc, const float4& raw) {
    const __half2* q = reinterpret_cast<const __half2*>(&raw);
    float2 f0 = __half22float2(q[0]);
    float2 f1 = __half22float2(q[1]);
    float2 f2 = __half22float2(q[2]);
    float2 f3 = __half22float2(q[3]);
    acc[0] += f0.x; acc[1] += f0.y;
    acc[2] += f1.x; acc[3] += f1.y;
    acc[4] += f2.x; acc[5] += f2.y;
    acc[6] += f3.x; acc[7] += f3.y;
}

template <bool RELU, bool OUTF>
__global__ void __launch_bounds__(256) layer_kernel(
        const __half2* __restrict__ hin,
        const float* __restrict__ W,
        const float* __restrict__ b,
        float* __restrict__ outf,
        __half2* __restrict__ outh) {
    __shared__ ull  Wq[D * 34];          // Wqf[c*68 + k] = W[k][c], 272B stride
    __shared__ float vsm[TR * D];
    __shared__ float bs[D];

    int tid = threadIdx.x;
    int rowBase = blockIdx.x * TR;

    float* Wqf = reinterpret_cast<float*>(Wq);
    for (int i = tid; i < D * D; i += 256) {
        int k = i >> 6, c = i & 63;
        Wqf[c * 68 + k] = W[i];
    }
    if (tid < D) bs[tid] = b[tid];

    int warp = tid >> 5;
    int lane = tid & 31;
    int r0 = warp * 8;
    int qw = lane >> 3;      // edge group 0..3
    int hl = lane & 7;       // dim slot: dims 8hl..8hl+7

    // ---- gather + normalize into vsm ----
    const float4* hp = reinterpret_cast<const float4*>(hin);   // 8 float4/row
#pragma unroll 1
    for (int r = 0; r < 8; r++) {
        int n = rowBase + r0 + r;
        if (n >= N_NODES) break;
        int beg = __ldg(g_off + n);
        int num = __ldg(g_num + n);
        float acc[8] = {0.f, 0.f, 0.f, 0.f, 0.f, 0.f, 0.f, 0.f};
        if (qw == 0) {                                   // self row
            float4 raw = __ldg(hp + (size_t)n * 8 + hl);
            acc_half8(acc, raw);
        }
        int j = beg, end = beg + num;
#pragma unroll 1
        for (; j + 8 <= end; j += 8) {
            int i0 = __ldg(g_esrc + j + qw);
            int i1 = __ldg(g_esrc + j + 4 + qw);
            float4 a0 = __ldg(hp + (size_t)i0 * 8 + hl);
            float4 a1 = __ldg(hp + (size_t)i1 * 8 + hl);
            acc_half8(acc, a0);
            acc_half8(acc, a1);
        }
        if (j + qw < end) {
            int s = __ldg(g_esrc + j + qw);
            float4 a = __ldg(hp + (size_t)s * 8 + hl);
            acc_half8(acc, a);
        }
        if (j + 4 + qw < end) {
            int s = __ldg(g_esrc + j + 4 + qw);
            float4 a = __ldg(hp + (size_t)s * 8 + hl);
            acc_half8(acc, a);
        }
        // merge the 4 edge groups (off the per-edge critical path)
#pragma unroll
        for (int d = 0; d < 8; d++) {
            acc[d] += __shfl_xor_sync(0xffffffffu, acc[d], 8);
            acc[d] += __shfl_xor_sync(0xffffffffu, acc[d], 16);
        }
        if (qw == 0) {
            float iv = __ldg(g_inv + n);
            float4* vp = reinterpret_cast<float4*>(vsm + (r0 + r) * D + 8 * hl);
            vp[0] = make_float4(acc[0] * iv, acc[1] * iv, acc[2] * iv, acc[3] * iv);
            vp[1] = make_float4(acc[4] * iv, acc[5] * iv, acc[6] * iv, acc[7] * iv);
        }
    }
    __syncthreads();

    // ---- FFMA2 GEMM: out[rows, :] = vsm @ W + b ----
    ull acc_a[8], acc_b[8];
#pragma unroll
    for (int r = 0; r < 8; r++) { acc_a[r] = 0ull; acc_b[r] = 0ull; }

    const float4* wa4 = reinterpret_cast<const float4*>(Wqf + lane * 68);
    const float4* wb4 = reinterpret_cast<const float4*>(Wqf + (lane + 32) * 68);

#pragma unroll
    for (int k4 = 0; k4 < 16; k4++) {
        float4 wav = wa4[k4];
        float4 wbv = wb4[k4];
        ull wa0 = reinterpret_cast<const ull*>(&wav)[0];
        ull wa1 = reinterpret_cast<const ull*>(&wav)[1];
        ull wb0 = reinterpret_cast<const ull*>(&wbv)[0];
        ull wb1 = reinterpret_cast<const ull*>(&wbv)[1];
#pragma unroll
        for (int r = 0; r < 8; r++) {
            float4 v = *reinterpret_cast<const float4*>(vsm + (r0 + r) * D + k4 * 4);
            ull v0 = reinterpret_cast<const ull*>(&v)[0];
            ull v1 = reinterpret_cast<const ull*>(&v)[1];
            ffma2(acc_a[r], v0, wa0);
            ffma2(acc_a[r], v1, wa1);
            ffma2(acc_b[r], v0, wb0);
            ffma2(acc_b[r], v1, wb1);
        }
    }

    float bias0 = bs[lane], bias1 = bs[lane + 32];
#pragma unroll
    for (int r = 0; r < 8; r++) {
        int row = rowBase + r0 + r;
        if (row < N_NODES) {
            float2 pa = *reinterpret_cast<float2*>(&acc_a[r]);
            float2 pb = *reinterpret_cast<float2*>(&acc_b[r]);
            float o0 = pa.x + pa.y + bias0;
            float o1 = pb.x + pb.y + bias1;
            if (RELU) { o0 = fmaxf(o0, 0.f); o1 = fmaxf(o1, 0.f); }
            if (OUTF) {
                outf[(size_t)row * D + lane]      = o0;
                outf[(size_t)row * D + lane + 32] = o1;
            } else {
                __half* oh = reinterpret_cast<__half*>(outh) + (size_t)row * D;
                oh[lane]      = __float2half_rn(o0);
                oh[lane + 32] = __float2half_rn(o1);
            }
        }
    }
}

// ---------------------------------------------------------------------------
extern "C" void kernel_launch(void* const* d_in, const int* in_sizes, int n_in,
                              void* d_out, int out_size) {
    const float* x   = (const float*)d_in[0];
    const int*   src = (const int*)  d_in[1];
    const int*   dst = (const int*)  d_in[2];
    const float* W0  = (const float*)d_in[3];
    const float* b0  = (const float*)d_in[4];
    const float* W1  = (const float*)d_in[5];
    const float* b1  = (const float*)d_in[6];
    const float* W2  = (const float*)d_in[7];
    const float* b2  = (const float*)d_in[8];
    float* out = (float*)d_out;

    __half2* hx; cudaGetSymbolAddress((void**)&hx, g_hx);
    __half2* h1; cudaGetSymbolAddress((void**)&h1, g_h1);
    __half2* h2; cudaGetSymbolAddress((void**)&h2, g_h2);

    const int edge_grid  = (N_EDGES + 255) / 256;
    const int layer_grid = (N_NODES + TR - 1) / TR;   // 782
    const int cvt_grid   = (N_NODES * (D / 2) + 255) / 256;

    // CSR build (full-chip 3-phase scan) + fp16 conversion of x
    cvt_kernel<<<cvt_grid, 256>>>(x);
    count_kernel<<<edge_grid, 256>>>(dst);
    scanA_kernel<<<SCAN_GRID, SCAN_B>>>();
    scanB_kernel<<<1, SCAN_B>>>();
    scanC_kernel<<<SCAN_GRID, SCAN_B>>>();
    fill_kernel<<<edge_grid, 256>>>(src, dst);

    layer_kernel<true,  false><<<layer_grid, 256>>>(hx, W0, b0, nullptr, h1);
    layer_kernel<true,  false><<<layer_grid, 256>>>(h1, W1, b1, nullptr, h2);
    layer_kernel<false, true ><<<layer_grid, 256>>>(h2, W2, b2, out, nullptr);
}

// round 13
// speedup vs baseline: 1.5769x; 1.0716x over previous
#include <cuda_runtime.h>
#include <cuda_fp16.h>

#define N_NODES 50000
#define N_EDGES 800000
#define D 64
#define TR 64            // dst rows per layer block
#define SCAN_B 256
#define SCAN_GRID ((N_NODES + SCAN_B - 1) / SCAN_B)   // 196

typedef unsigned long long ull;

// Scratch (__device__ globals: zero-initialized at load; every kernel restores
// its preconditions so the captured graph replays deterministically)
__device__ int    g_cnt[N_NODES];      // degree counters (zeroed each call by scanC)
__device__ int    g_off[N_NODES];      // CSR exclusive offsets
__device__ int    g_cur[N_NODES];      // fill cursors
__device__ int    g_num[N_NODES];      // degree snapshot
__device__ float  g_inv[N_NODES];      // 1/(deg+1)
__device__ int    g_btot[SCAN_GRID];   // per-block totals
__device__ int    g_esrc[N_EDGES];     // CSR column (src) indices
__device__ __half2 g_hx[(size_t)N_NODES * D / 2];   // fp16 copy of x
__device__ __half2 g_h1[(size_t)N_NODES * D / 2];   // fp16 intermediate h1
__device__ __half2 g_h2[(size_t)N_NODES * D / 2];   // fp16 intermediate h2

// packed f32x2 fma: d = a*b + d on (lo,hi) pairs (FFMA2, rt_SMSP=1)
__device__ __forceinline__ void ffma2(ull& d, ull a, ull b) {
    asm("fma.rn.f32x2 %0, %1, %2, %0;" : "+l"(d) : "l"(a), "l"(b));
}

// ---------------------------------------------------------------------------
// 0) convert x to fp16 once per call
__global__ void cvt_kernel(const float* __restrict__ x) {
    int i = blockIdx.x * blockDim.x + threadIdx.x;   // over N*D/2 half2s
    if (i < N_NODES * (D / 2)) {
        float2 v = __ldg(reinterpret_cast<const float2*>(x) + i);
        g_hx[i] = __floats2half2_rn(v.x, v.y);
    }
}

// 1) count in-degrees
__global__ void count_kernel(const int* __restrict__ dst) {
    int e = blockIdx.x * blockDim.x + threadIdx.x;
    if (e < N_EDGES) atomicAdd(&g_cnt[dst[e]], 1);
}

// 2a) per-block scan: local exclusive prefix -> g_off, block total -> g_btot
__global__ void __launch_bounds__(SCAN_B) scanA_kernel() {
    __shared__ int ps[SCAN_B];
    int t = threadIdx.x;
    int n = blockIdx.x * SCAN_B + t;
    int c = (n < N_NODES) ? g_cnt[n] : 0;
    ps[t] = c;
    __syncthreads();
#pragma unroll
    for (int off = 1; off < SCAN_B; off <<= 1) {
        int v = (t >= off) ? ps[t - off] : 0;
        __syncthreads();
        ps[t] += v;
        __syncthreads();
    }
    if (n < N_NODES) {
        g_off[n] = ps[t] - c;          // local exclusive
        g_num[n] = c;
    }
    if (t == SCAN_B - 1) g_btot[blockIdx.x] = ps[t];
}

// 2b) finalize: every block redundantly scans the 196 block totals in smem
//     (cheap), takes its own base, then writes offsets/cursors/inv and zeros
//     counters for the next replay. (Replaces the separate scanB launch.)
__global__ void __launch_bounds__(SCAN_B) scanC_kernel() {
    __shared__ int ps[SCAN_B];
    int t = threadIdx.x;
    int c = (t < SCAN_GRID) ? g_btot[t] : 0;
    ps[t] = c;
    __syncthreads();
#pragma unroll
    for (int off = 1; off < SCAN_B; off <<= 1) {
        int v = (t >= off) ? ps[t - off] : 0;
        __syncthreads();
        ps[t] += v;
        __syncthreads();
    }
    int bbase = (blockIdx.x == 0) ? 0 : ps[blockIdx.x - 1];
    int n = blockIdx.x * SCAN_B + t;
    if (n < N_NODES) {
        int off = g_off[n] + bbase;
        g_off[n] = off;
        g_cur[n] = off;
        g_inv[n] = 1.0f / (float)(g_num[n] + 1);
        g_cnt[n] = 0;                  // ready for next replay
    }
}

// 3) bucket-fill CSR column indices
__global__ void fill_kernel(const int* __restrict__ src,
                            const int* __restrict__ dst) {
    int e = blockIdx.x * blockDim.x + threadIdx.x;
    if (e < N_EDGES) {
        int pos = atomicAdd(&g_cur[dst[e]], 1);
        g_esrc[pos] = src[e];
    }
}

// ---------------------------------------------------------------------------
// Fused layer, fp16 features. Warp owns 8 dst rows; lane group qw=lane>>3
// takes edge j+qw, slot hl=lane&7 covers dims 8hl..8hl+7. Edge indices are
// software-pipelined (next iteration's idx loads issue before the current
// rows are consumed) so idx latency overlaps row-load latency. The gather ->
// GEMM handoff is warp-local (vsm rows are warp-private): __syncwarp only,
// no block barrier after gather. FFMA2 GEMM + bias(+relu); fp16 out for
// intermediate layers, fp32 for the final layer.
__device__ __forceinline__ void acc_half8(float* acc, const float4& raw) {
    const __half2* q = reinterpret_cast<const __half2*>(&raw);
    float2 f0 = __half22float2(q[0]);
    float2 f1 = __half22float2(q[1]);
    float2 f2 = __half22float2(q[2]);
    float2 f3 = __half22float2(q[3]);
    acc[0] += f0.x; acc[1] += f0.y;
    acc[2] += f1.x; acc[3] += f1.y;
    acc[4] += f2.x; acc[5] += f2.y;
    acc[6] += f3.x; acc[7] += f3.y;
}

template <bool RELU, bool OUTF>
__global__ void __launch_bounds__(256) layer_kernel(
        const __half2* __restrict__ hin,
        const float* __restrict__ W,
        const float* __restrict__ b,
        float* __restrict__ outf,
        __half2* __restrict__ outh) {
    __shared__ ull  Wq[D * 34];          // Wqf[c*68 + k] = W[k][c], 272B stride
    __shared__ float vsm[TR * D];
    __shared__ float bs[D];

    int tid = threadIdx.x;
    int rowBase = blockIdx.x * TR;

    float* Wqf = reinterpret_cast<float*>(Wq);
    for (int i = tid; i < D * D; i += 256) {
        int k = i >> 6, c = i & 63;
        Wqf[c * 68 + k] = W[i];
    }
    if (tid < D) bs[tid] = b[tid];
    __syncthreads();                      // Wq/bs visible to all warps

    int warp = tid >> 5;
    int lane = tid & 31;
    int r0 = warp * 8;
    int qw = lane >> 3;      // edge group 0..3
    int hl = lane & 7;       // dim slot: dims 8hl..8hl+7

    // ---- gather + normalize into vsm (warp-private rows) ----
    const float4* hp = reinterpret_cast<const float4*>(hin);   // 8 float4/row
#pragma unroll 1
    for (int r = 0; r < 8; r++) {
        int n = rowBase + r0 + r;
        if (n >= N_NODES) break;
        int beg = __ldg(g_off + n);
        int num = __ldg(g_num + n);
        float acc[8] = {0.f, 0.f, 0.f, 0.f, 0.f, 0.f, 0.f, 0.f};
        if (qw == 0) {                                   // self row
            float4 raw = __ldg(hp + (size_t)n * 8 + hl);
            acc_half8(acc, raw);
        }
        int j = beg, end = beg + num;
        // software-pipelined 8-edge chunks: prefetch next indices before
        // consuming current rows
        int i0 = 0, i1 = 0;
        bool have = (j + 8 <= end);
        if (have) {
            i0 = __ldg(g_esrc + j + qw);
            i1 = __ldg(g_esrc + j + 4 + qw);
        }
#pragma unroll 1
        while (have) {
            float4 a0 = __ldg(hp + (size_t)i0 * 8 + hl);
            float4 a1 = __ldg(hp + (size_t)i1 * 8 + hl);
            j += 8;
            have = (j + 8 <= end);
            if (have) {
                i0 = __ldg(g_esrc + j + qw);           // prefetch next chunk
                i1 = __ldg(g_esrc + j + 4 + qw);
            }
            acc_half8(acc, a0);
            acc_half8(acc, a1);
        }
        if (j + qw < end) {
            int s = __ldg(g_esrc + j + qw);
            float4 a = __ldg(hp + (size_t)s * 8 + hl);
            acc_half8(acc, a);
        }
        if (j + 4 + qw < end) {
            int s = __ldg(g_esrc + j + 4 + qw);
            float4 a = __ldg(hp + (size_t)s * 8 + hl);
            acc_half8(acc, a);
        }
        // merge the 4 edge groups (off the per-edge critical path)
#pragma unroll
        for (int d = 0; d < 8; d++) {
            acc[d] += __shfl_xor_sync(0xffffffffu, acc[d], 8);
            acc[d] += __shfl_xor_sync(0xffffffffu, acc[d], 16);
        }
        if (qw == 0) {
            float iv = __ldg(g_inv + n);
            float4* vp = reinterpret_cast<float4*>(vsm + (r0 + r) * D + 8 * hl);
            vp[0] = make_float4(acc[0] * iv, acc[1] * iv, acc[2] * iv, acc[3] * iv);
            vp[1] = make_float4(acc[4] * iv, acc[5] * iv, acc[6] * iv, acc[7] * iv);
        }
    }
    __syncwarp();                         // vsm rows are warp-private

    // ---- FFMA2 GEMM: out[rows, :] = vsm @ W + b ----
    ull acc_a[8], acc_b[8];
#pragma unroll
    for (int r = 0; r < 8; r++) { acc_a[r] = 0ull; acc_b[r] = 0ull; }

    const float4* wa4 = reinterpret_cast<const float4*>(Wqf + lane * 68);
    const float4* wb4 = reinterpret_cast<const float4*>(Wqf + (lane + 32) * 68);

#pragma unroll
    for (int k4 = 0; k4 < 16; k4++) {
        float4 wav = wa4[k4];
        float4 wbv = wb4[k4];
        ull wa0 = reinterpret_cast<const ull*>(&wav)[0];
        ull wa1 = reinterpret_cast<const ull*>(&wav)[1];
        ull wb0 = reinterpret_cast<const ull*>(&wbv)[0];
        ull wb1 = reinterpret_cast<const ull*>(&wbv)[1];
#pragma unroll
        for (int r = 0; r < 8; r++) {
            float4 v = *reinterpret_cast<const float4*>(vsm + (r0 + r) * D + k4 * 4);
            ull v0 = reinterpret_cast<const ull*>(&v)[0];
            ull v1 = reinterpret_cast<const ull*>(&v)[1];
            ffma2(acc_a[r], v0, wa0);
            ffma2(acc_a[r], v1, wa1);
            ffma2(acc_b[r], v0, wb0);
            ffma2(acc_b[r], v1, wb1);
        }
    }

    float bias0 = bs[lane], bias1 = bs[lane + 32];
#pragma unroll
    for (int r = 0; r < 8; r++) {
        int row = rowBase + r0 + r;
        if (row < N_NODES) {
            float2 pa = *reinterpret_cast<float2*>(&acc_a[r]);
            float2 pb = *reinterpret_cast<float2*>(&acc_b[r]);
            float o0 = pa.x + pa.y + bias0;
            float o1 = pb.x + pb.y + bias1;
            if (RELU) { o0 = fmaxf(o0, 0.f); o1 = fmaxf(o1, 0.f); }
            if (OUTF) {
                outf[(size_t)row * D + lane]      = o0;
                outf[(size_t)row * D + lane + 32] = o1;
            } else {
                __half* oh = reinterpret_cast<__half*>(outh) + (size_t)row * D;
                oh[lane]      = __float2half_rn(o0);
                oh[lane + 32] = __float2half_rn(o1);
            }
        }
    }
}

// ---------------------------------------------------------------------------
extern "C" void kernel_launch(void* const* d_in, const int* in_sizes, int n_in,
                              void* d_out, int out_size) {
    const float* x   = (const float*)d_in[0];
    const int*   src = (const int*)  d_in[1];
    const int*   dst = (const int*)  d_in[2];
    const float* W0  = (const float*)d_in[3];
    const float* b0  = (const float*)d_in[4];
    const float* W1  = (const float*)d_in[5];
    const float* b1  = (const float*)d_in[6];
    const float* W2  = (const float*)d_in[7];
    const float* b2  = (const float*)d_in[8];
    float* out = (float*)d_out;

    __half2* hx; cudaGetSymbolAddress((void**)&hx, g_hx);
    __half2* h1; cudaGetSymbolAddress((void**)&h1, g_h1);
    __half2* h2; cudaGetSymbolAddress((void**)&h2, g_h2);

    const int edge_grid  = (N_EDGES + 255) / 256;
    const int layer_grid = (N_NODES + TR - 1) / TR;   // 782
    const int cvt_grid   = (N_NODES * (D / 2) + 255) / 256;

    // CSR build (count -> per-block scan -> fused finalize) + fp16 x
    cvt_kernel<<<cvt_grid, 256>>>(x);
    count_kernel<<<edge_grid, 256>>>(dst);
    scanA_kernel<<<SCAN_GRID, SCAN_B>>>();
    scanC_kernel<<<SCAN_GRID, SCAN_B>>>();
    fill_kernel<<<edge_grid, 256>>>(src, dst);

    layer_kernel<true,  false><<<layer_grid, 256>>>(hx, W0, b0, nullptr, h1);
    layer_kernel<true,  false><<<layer_grid, 256>>>(h1, W1, b1, nullptr, h2);
    layer_kernel<false, true ><<<layer_grid, 256>>>(h2, W2, b2, out, nullptr);
}

// round 15
// speedup vs baseline: 1.6225x; 1.0289x over previous
#include <cuda_runtime.h>
#include <cuda_fp16.h>

#define N_NODES 50000
#define N_EDGES 800000
#define D 64
#define TR 64            // dst rows per layer block
#define SCAN_B 256
#define SCAN_GRID ((N_NODES + SCAN_B - 1) / SCAN_B)   // 196

typedef unsigned long long ull;
typedef unsigned short u16;

// Scratch (__device__ globals: zero-initialized at load; every kernel restores
// its preconditions so the captured graph replays deterministically)
__device__ int    g_cnt[N_NODES];      // degree counters (zeroed each call by scanC)
__device__ int    g_off[N_NODES];      // CSR exclusive offsets
__device__ int    g_cur[N_NODES];      // fill cursors
__device__ int    g_num[N_NODES];      // degree snapshot
__device__ float  g_inv[N_NODES];      // 1/(deg+1)
__device__ int    g_btot[SCAN_GRID];   // per-block totals
__device__ u16    g_esrc[N_EDGES];     // CSR column (src) indices, 16-bit (N<65536)
__device__ __half2 g_hx[(size_t)N_NODES * D / 2];   // fp16 copy of x
__device__ __half2 g_h1[(size_t)N_NODES * D / 2];   // fp16 intermediate h1
__device__ __half2 g_h2[(size_t)N_NODES * D / 2];   // fp16 intermediate h2

// packed f32x2 fma: d = a*b + d on (lo,hi) pairs (FFMA2, rt_SMSP=1)
__device__ __forceinline__ void ffma2(ull& d, ull a, ull b) {
    asm("fma.rn.f32x2 %0, %1, %2, %0;" : "+l"(d) : "l"(a), "l"(b));
}

// ---------------------------------------------------------------------------
// 0+1) fused: convert x to fp16 AND count in-degrees (one launch; the atomic
//      stream overlaps the cvt loads). Grid covers N*D/2 = 1.6M threads.
__global__ void cvt_count_kernel(const float* __restrict__ x,
                                 const int* __restrict__ dst) {
    int i = blockIdx.x * blockDim.x + threadIdx.x;
    if (i < N_NODES * (D / 2)) {
        float2 v = __ldg(reinterpret_cast<const float2*>(x) + i);
        g_hx[i] = __floats2half2_rn(v.x, v.y);
    }
    if (i < N_EDGES) atomicAdd(&g_cnt[dst[i]], 1);
}

// 2a) per-block scan: local exclusive prefix -> g_off, block total -> g_btot
__global__ void __launch_bounds__(SCAN_B) scanA_kernel() {
    __shared__ int ps[SCAN_B];
    int t = threadIdx.x;
    int n = blockIdx.x * SCAN_B + t;
    int c = (n < N_NODES) ? g_cnt[n] : 0;
    ps[t] = c;
    __syncthreads();
#pragma unroll
    for (int off = 1; off < SCAN_B; off <<= 1) {
        int v = (t >= off) ? ps[t - off] : 0;
        __syncthreads();
        ps[t] += v;
        __syncthreads();
    }
    if (n < N_NODES) {
        g_off[n] = ps[t] - c;          // local exclusive
        g_num[n] = c;
    }
    if (t == SCAN_B - 1) g_btot[blockIdx.x] = ps[t];
}

// 2b) finalize: every block redundantly scans the 196 block totals in smem,
//     takes its own base, writes offsets/cursors/inv, zeros counters.
__global__ void __launch_bounds__(SCAN_B) scanC_kernel() {
    __shared__ int ps[SCAN_B];
    int t = threadIdx.x;
    int c = (t < SCAN_GRID) ? g_btot[t] : 0;
    ps[t] = c;
    __syncthreads();
#pragma unroll
    for (int off = 1; off < SCAN_B; off <<= 1) {
        int v = (t >= off) ? ps[t - off] : 0;
        __syncthreads();
        ps[t] += v;
        __syncthreads();
    }
    int bbase = (blockIdx.x == 0) ? 0 : ps[blockIdx.x - 1];
    int n = blockIdx.x * SCAN_B + t;
    if (n < N_NODES) {
        int off = g_off[n] + bbase;
        g_off[n] = off;
        g_cur[n] = off;
        g_inv[n] = 1.0f / (float)(g_num[n] + 1);
        g_cnt[n] = 0;                  // ready for next replay
    }
}

// 3) bucket-fill CSR column indices (16-bit)
__global__ void fill_kernel(const int* __restrict__ src,
                            const int* __restrict__ dst) {
    int e = blockIdx.x * blockDim.x + threadIdx.x;
    if (e < N_EDGES) {
        int pos = atomicAdd(&g_cur[dst[e]], 1);
        g_esrc[pos] = (u16)src[e];
    }
}

// ---------------------------------------------------------------------------
// Fused layer, fp16 features. Warp owns 8 dst rows; lane group qw=lane>>3
// takes edge j+qw, slot hl=lane&7 covers dims 8hl..8hl+7. Gather is depth-2
// software-pipelined: chunk k+1's ROW loads are in flight while chunk k is
// accumulated, and chunk k+2's indices prefetch behind them. Warp-local
// handoff (vsm rows warp-private, __syncwarp only), then FFMA2 GEMM.
__device__ __forceinline__ void acc_half8(float* acc, const float4& raw) {
    const __half2* q = reinterpret_cast<const __half2*>(&raw);
    float2 f0 = __half22float2(q[0]);
    float2 f1 = __half22float2(q[1]);
    float2 f2 = __half22float2(q[2]);
    float2 f3 = __half22float2(q[3]);
    acc[0] += f0.x; acc[1] += f0.y;
    acc[2] += f1.x; acc[3] += f1.y;
    acc[4] += f2.x; acc[5] += f2.y;
    acc[6] += f3.x; acc[7] += f3.y;
}

template <bool RELU, bool OUTF>
__global__ void __launch_bounds__(256) layer_kernel(
        const __half2* __restrict__ hin,
        const float* __restrict__ W,
        const float* __restrict__ b,
        float* __restrict__ outf,
        __half2* __restrict__ outh) {
    __shared__ ull  Wq[D * 34];          // Wqf[c*68 + k] = W[k][c], 272B stride
    __shared__ float vsm[TR * D];
    __shared__ float bs[D];

    int tid = threadIdx.x;
    int rowBase = blockIdx.x * TR;

    float* Wqf = reinterpret_cast<float*>(Wq);
    for (int i = tid; i < D * D; i += 256) {
        int k = i >> 6, c = i & 63;
        Wqf[c * 68 + k] = W[i];
    }
    if (tid < D) bs[tid] = b[tid];
    __syncthreads();                      // Wq/bs visible to all warps

    int warp = tid >> 5;
    int lane = tid & 31;
    int r0 = warp * 8;
    int qw = lane >> 3;      // edge group 0..3
    int hl = lane & 7;       // dim slot: dims 8hl..8hl+7

    // ---- gather + normalize into vsm (warp-private rows) ----
    const float4* hp = reinterpret_cast<const float4*>(hin);   // 8 float4/row
#pragma unroll 1
    for (int r = 0; r < 8; r++) {
        int n = rowBase + r0 + r;
        if (n >= N_NODES) break;
        int beg = __ldg(g_off + n);
        int num = __ldg(g_num + n);
        float acc[8] = {0.f, 0.f, 0.f, 0.f, 0.f, 0.f, 0.f, 0.f};
        if (qw == 0) {                                   // self row
            float4 raw = __ldg(hp + (size_t)n * 8 + hl);
            acc_half8(acc, raw);
        }
        int j = beg, end = beg + num;
        // depth-2 pipeline: rows of chunk k+1 load while chunk k accumulates
        float4 a0 = make_float4(0.f, 0.f, 0.f, 0.f), a1 = a0;
        int i0 = 0, i1 = 0;
        bool have = (j + 8 <= end);
        if (have) {
            int p0 = __ldg(g_esrc + j + qw);
            int p1 = __ldg(g_esrc + j + 4 + qw);
            a0 = __ldg(hp + (size_t)p0 * 8 + hl);
            a1 = __ldg(hp + (size_t)p1 * 8 + hl);
            j += 8;
            if (j + 8 <= end) {
                i0 = __ldg(g_esrc + j + qw);
                i1 = __ldg(g_esrc + j + 4 + qw);
            }
        }
#pragma unroll 1
        while (have) {
            bool haveN = (j + 8 <= end);
            float4 b0 = make_float4(0.f, 0.f, 0.f, 0.f), b1 = b0;
            if (haveN) {
                b0 = __ldg(hp + (size_t)i0 * 8 + hl);   // next chunk rows
                b1 = __ldg(hp + (size_t)i1 * 8 + hl);
                j += 8;
                if (j + 8 <= end) {                      // idx two chunks ahead
                    i0 = __ldg(g_esrc + j + qw);
                    i1 = __ldg(g_esrc + j + 4 + qw);
                }
            }
            acc_half8(acc, a0);                          // consume current
            acc_half8(acc, a1);
            a0 = b0; a1 = b1;
            have = haveN;
        }
        if (j + qw < end) {
            int s = __ldg(g_esrc + j + qw);
            float4 a = __ldg(hp + (size_t)s * 8 + hl);
            acc_half8(acc, a);
        }
        if (j + 4 + qw < end) {
            int s = __ldg(g_esrc + j + 4 + qw);
            float4 a = __ldg(hp + (size_t)s * 8 + hl);
            acc_half8(acc, a);
        }
        // merge the 4 edge groups (off the per-edge critical path)
#pragma unroll
        for (int d = 0; d < 8; d++) {
            acc[d] += __shfl_xor_sync(0xffffffffu, acc[d], 8);
            acc[d] += __shfl_xor_sync(0xffffffffu, acc[d], 16);
        }
        if (qw == 0) {
            float iv = __ldg(g_inv + n);
            float4* vp = reinterpret_cast<float4*>(vsm + (r0 + r) * D + 8 * hl);
            vp[0] = make_float4(acc[0] * iv, acc[1] * iv, acc[2] * iv, acc[3] * iv);
            vp[1] = make_float4(acc[4] * iv, acc[5] * iv, acc[6] * iv, acc[7] * iv);
        }
    }
    __syncwarp();                         // vsm rows are warp-private

    // ---- FFMA2 GEMM: out[rows, :] = vsm @ W + b ----
    ull acc_a[8], acc_b[8];
#pragma unroll
    for (int r = 0; r < 8; r++) { acc_a[r] = 0ull; acc_b[r] = 0ull; }

    const float4* wa4 = reinterpret_cast<const float4*>(Wqf + lane * 68);
    const float4* wb4 = reinterpret_cast<const float4*>(Wqf + (lane + 32) * 68);

#pragma unroll
    for (int k4 = 0; k4 < 16; k4++) {
        float4 wav = wa4[k4];
        float4 wbv = wb4[k4];
        ull wa0 = reinterpret_cast<const ull*>(&wav)[0];
        ull wa1 = reinterpret_cast<const ull*>(&wav)[1];
        ull wb0 = reinterpret_cast<const ull*>(&wbv)[0];
        ull wb1 = reinterpret_cast<const ull*>(&wbv)[1];
#pragma unroll
        for (int r = 0; r < 8; r++) {
            float4 v = *reinterpret_cast<const float4*>(vsm + (r0 + r) * D + k4 * 4);
            ull v0 = reinterpret_cast<const ull*>(&v)[0];
            ull v1 = reinterpret_cast<const ull*>(&v)[1];
            ffma2(acc_a[r], v0, wa0);
            ffma2(acc_a[r], v1, wa1);
            ffma2(acc_b[r], v0, wb0);
            ffma2(acc_b[r], v1, wb1);
        }
    }

    float bias0 = bs[lane], bias1 = bs[lane + 32];
#pragma unroll
    for (int r = 0; r < 8; r++) {
        int row = rowBase + r0 + r;
        if (row < N_NODES) {
            float2 pa = *reinterpret_cast<float2*>(&acc_a[r]);
            float2 pb = *reinterpret_cast<float2*>(&acc_b[r]);
            float o0 = pa.x + pa.y + bias0;
            float o1 = pb.x + pb.y + bias1;
            if (RELU) { o0 = fmaxf(o0, 0.f); o1 = fmaxf(o1, 0.f); }
            if (OUTF) {
                outf[(size_t)row * D + lane]      = o0;
                outf[(size_t)row * D + lane + 32] = o1;
            } else {
                __half* oh = reinterpret_cast<__half*>(outh) + (size_t)row * D;
                oh[lane]      = __float2half_rn(o0);
                oh[lane + 32] = __float2half_rn(o1);
            }
        }
    }
}

// ---------------------------------------------------------------------------
extern "C" void kernel_launch(void* const* d_in, const int* in_sizes, int n_in,
                              void* d_out, int out_size) {
    const float* x   = (const float*)d_in[0];
    const int*   src = (const int*)  d_in[1];
    const int*   dst = (const int*)  d_in[2];
    const float* W0  = (const float*)d_in[3];
    const float* b0  = (const float*)d_in[4];
    const float* W1  = (const float*)d_in[5];
    const float* b1  = (const float*)d_in[6];
    const float* W2  = (const float*)d_in[7];
    const float* b2  = (const float*)d_in[8];
    float* out = (float*)d_out;

    __half2* hx; cudaGetSymbolAddress((void**)&hx, g_hx);
    __half2* h1; cudaGetSymbolAddress((void**)&h1, g_h1);
    __half2* h2; cudaGetSymbolAddress((void**)&h2, g_h2);

    const int edge_grid  = (N_EDGES + 255) / 256;
    const int layer_grid = (N_NODES + TR - 1) / TR;   // 782
    const int cc_grid    = (N_NODES * (D / 2) + 255) / 256;   // covers cvt+count

    // CSR build (fused cvt+count -> per-block scan -> fused finalize -> fill)
    cvt_count_kernel<<<cc_grid, 256>>>(x, dst);
    scanA_kernel<<<SCAN_GRID, SCAN_B>>>();
    scanC_kernel<<<SCAN_GRID, SCAN_B>>>();
    fill_kernel<<<edge_grid, 256>>>(src, dst);

    layer_kernel<true,  false><<<layer_grid, 256>>>(hx, W0, b0, nullptr, h1);
    layer_kernel<true,  false><<<layer_grid, 256>>>(h1, W1, b1, nullptr, h2);
    layer_kernel<false, true ><<<layer_grid, 256>>>(h2, W2, b2, out, nullptr);
}

// round 16
// speedup vs baseline: 1.6509x; 1.0175x over previous
#include <cuda_runtime.h>
#include <cuda_fp16.h>

#define N_NODES 50000
#define N_EDGES 800000
#define D 64
#define SCAN_B 256
#define SCAN_GRID ((N_NODES + SCAN_B - 1) / SCAN_B)   // 196
#define NT ((N_NODES + 7) / 8)                        // 6250 8-row tiles
#define LAYER_GRID 444                                // 3 blocks/SM persistent

typedef unsigned long long ull;
typedef unsigned short u16;

// Scratch (__device__ globals: zero-initialized at load; every kernel restores
// its preconditions so the captured graph replays deterministically)
__device__ int    g_cnt[N_NODES];      // degree counters (zeroed each call by scanC)
__device__ int    g_off[N_NODES];      // CSR exclusive offsets
__device__ int    g_cur[N_NODES];      // fill cursors
__device__ int    g_num[N_NODES];      // degree snapshot
__device__ float  g_inv[N_NODES];      // 1/(deg+1)
__device__ int    g_btot[SCAN_GRID];   // per-block totals
__device__ int    g_wq[4];             // per-layer work-queue counters (zeroed by scanC)
__device__ u16    g_esrc[N_EDGES];     // CSR column (src) indices, 16-bit (N<65536)
__device__ __half2 g_hx[(size_t)N_NODES * D / 2];   // fp16 copy of x
__device__ __half2 g_h1[(size_t)N_NODES * D / 2];   // fp16 intermediate h1
__device__ __half2 g_h2[(size_t)N_NODES * D / 2];   // fp16 intermediate h2

// packed f32x2 fma: d = a*b + d on (lo,hi) pairs (FFMA2, rt_SMSP=1)
__device__ __forceinline__ void ffma2(ull& d, ull a, ull b) {
    asm("fma.rn.f32x2 %0, %1, %2, %0;" : "+l"(d) : "l"(a), "l"(b));
}

// ---------------------------------------------------------------------------
// 0+1) fused: convert x to fp16 AND count in-degrees (one launch)
__global__ void cvt_count_kernel(const float* __restrict__ x,
                                 const int* __restrict__ dst) {
    int i = blockIdx.x * blockDim.x + threadIdx.x;
    if (i < N_NODES * (D / 2)) {
        float2 v = __ldg(reinterpret_cast<const float2*>(x) + i);
        g_hx[i] = __floats2half2_rn(v.x, v.y);
    }
    if (i < N_EDGES) atomicAdd(&g_cnt[dst[i]], 1);
}

// 2a) per-block scan: local exclusive prefix -> g_off, block total -> g_btot
__global__ void __launch_bounds__(SCAN_B) scanA_kernel() {
    __shared__ int ps[SCAN_B];
    int t = threadIdx.x;
    int n = blockIdx.x * SCAN_B + t;
    int c = (n < N_NODES) ? g_cnt[n] : 0;
    ps[t] = c;
    __syncthreads();
#pragma unroll
    for (int off = 1; off < SCAN_B; off <<= 1) {
        int v = (t >= off) ? ps[t - off] : 0;
        __syncthreads();
        ps[t] += v;
        __syncthreads();
    }
    if (n < N_NODES) {
        g_off[n] = ps[t] - c;          // local exclusive
        g_num[n] = c;
    }
    if (t == SCAN_B - 1) g_btot[blockIdx.x] = ps[t];
}

// 2b) finalize: every block redundantly scans the 196 block totals in smem,
//     takes its own base, writes offsets/cursors/inv, zeros counters and the
//     layer work queues for the next replay.
__global__ void __launch_bounds__(SCAN_B) scanC_kernel() {
    __shared__ int ps[SCAN_B];
    int t = threadIdx.x;
    int c = (t < SCAN_GRID) ? g_btot[t] : 0;
    ps[t] = c;
    __syncthreads();
#pragma unroll
    for (int off = 1; off < SCAN_B; off <<= 1) {
        int v = (t >= off) ? ps[t - off] : 0;
        __syncthreads();
        ps[t] += v;
        __syncthreads();
    }
    int bbase = (blockIdx.x == 0) ? 0 : ps[blockIdx.x - 1];
    int n = blockIdx.x * SCAN_B + t;
    if (n < N_NODES) {
        int off = g_off[n] + bbase;
        g_off[n] = off;
        g_cur[n] = off;
        g_inv[n] = 1.0f / (float)(g_num[n] + 1);
        g_cnt[n] = 0;                  // ready for next replay
    }
    if (blockIdx.x == 0 && t < 4) g_wq[t] = 0;   // reset layer work queues
}

// 3) bucket-fill CSR column indices (16-bit)
__global__ void fill_kernel(const int* __restrict__ src,
                            const int* __restrict__ dst) {
    int e = blockIdx.x * blockDim.x + threadIdx.x;
    if (e < N_EDGES) {
        int pos = atomicAdd(&g_cur[dst[e]], 1);
        g_esrc[pos] = (u16)src[e];
    }
}

// ---------------------------------------------------------------------------
// Fused layer, fp16 features, persistent warps + dynamic tile queue.
// Each warp pulls 8-row tiles from g_wq[LAYER]; per tile: depth-2 pipelined
// gather into its private vsm slice, then FFMA2 GEMM + bias(+relu) and store.
// Degree imbalance smooths because heavy-tile warps simply pull fewer tiles.
__device__ __forceinline__ void acc_half8(float* acc, const float4& raw) {
    const __half2* q = reinterpret_cast<const __half2*>(&raw);
    float2 f0 = __half22float2(q[0]);
    float2 f1 = __half22float2(q[1]);
    float2 f2 = __half22float2(q[2]);
    float2 f3 = __half22float2(q[3]);
    acc[0] += f0.x; acc[1] += f0.y;
    acc[2] += f1.x; acc[3] += f1.y;
    acc[4] += f2.x; acc[5] += f2.y;
    acc[6] += f3.x; acc[7] += f3.y;
}

template <bool RELU, bool OUTF, int LAYER>
__global__ void __launch_bounds__(256) layer_kernel(
        const __half2* __restrict__ hin,
        const float* __restrict__ W,
        const float* __restrict__ b,
        float* __restrict__ outf,
        __half2* __restrict__ outh) {
    __shared__ ull  Wq[D * 34];          // Wqf[c*68 + k] = W[k][c], 272B stride
    __shared__ float vsm[64 * D];        // 8 warps x 8 rows
    __shared__ float bs[D];

    int tid = threadIdx.x;
    float* Wqf = reinterpret_cast<float*>(Wq);
    for (int i = tid; i < D * D; i += 256) {
        int k = i >> 6, c = i & 63;
        Wqf[c * 68 + k] = W[i];
    }
    if (tid < D) bs[tid] = b[tid];
    __syncthreads();                      // Wq/bs visible to all warps

    int warp = tid >> 5;
    int lane = tid & 31;
    int r0 = warp * 8;                    // this warp's vsm slice
    int qw = lane >> 3;      // edge group 0..3
    int hl = lane & 7;       // dim slot: dims 8hl..8hl+7

    const float4* hp = reinterpret_cast<const float4*>(hin);   // 8 float4/row
    const float4* wa4 = reinterpret_cast<const float4*>(Wqf + lane * 68);
    const float4* wb4 = reinterpret_cast<const float4*>(Wqf + (lane + 32) * 68);
    float bias0 = bs[lane], bias1 = bs[lane + 32];

    for (;;) {
        // ---- pull next 8-row tile from the queue ----
        int tile;
        if (lane == 0) tile = atomicAdd(&g_wq[LAYER], 1);
        tile = __shfl_sync(0xffffffffu, tile, 0);
        if (tile >= NT) break;
        int rowBase = tile * 8;

        // ---- gather + normalize into warp's vsm slice ----
#pragma unroll 1
        for (int r = 0; r < 8; r++) {
            int n = rowBase + r;
            if (n >= N_NODES) break;
            int beg = __ldg(g_off + n);
            int num = __ldg(g_num + n);
            float acc[8] = {0.f, 0.f, 0.f, 0.f, 0.f, 0.f, 0.f, 0.f};
            if (qw == 0) {                                   // self row
                float4 raw = __ldg(hp + (size_t)n * 8 + hl);
                acc_half8(acc, raw);
            }
            int j = beg, end = beg + num;
            // depth-2 pipeline: rows of chunk k+1 load while chunk k accumulates
            float4 a0 = make_float4(0.f, 0.f, 0.f, 0.f), a1 = a0;
            int i0 = 0, i1 = 0;
            bool have = (j + 8 <= end);
            if (have) {
                int p0 = __ldg(g_esrc + j + qw);
                int p1 = __ldg(g_esrc + j + 4 + qw);
                a0 = __ldg(hp + (size_t)p0 * 8 + hl);
                a1 = __ldg(hp + (size_t)p1 * 8 + hl);
                j += 8;
                if (j + 8 <= end) {
                    i0 = __ldg(g_esrc + j + qw);
                    i1 = __ldg(g_esrc + j + 4 + qw);
                }
            }
#pragma unroll 1
            while (have) {
                bool haveN = (j + 8 <= end);
                float4 b0 = make_float4(0.f, 0.f, 0.f, 0.f), b1 = b0;
                if (haveN) {
                    b0 = __ldg(hp + (size_t)i0 * 8 + hl);   // next chunk rows
                    b1 = __ldg(hp + (size_t)i1 * 8 + hl);
                    j += 8;
                    if (j + 8 <= end) {                      // idx two chunks ahead
                        i0 = __ldg(g_esrc + j + qw);
                        i1 = __ldg(g_esrc + j + 4 + qw);
                    }
                }
                acc_half8(acc, a0);                          // consume current
                acc_half8(acc, a1);
                a0 = b0; a1 = b1;
                have = haveN;
            }
            if (j + qw < end) {
                int s = __ldg(g_esrc + j + qw);
                float4 a = __ldg(hp + (size_t)s * 8 + hl);
                acc_half8(acc, a);
            }
            if (j + 4 + qw < end) {
                int s = __ldg(g_esrc + j + 4 + qw);
                float4 a = __ldg(hp + (size_t)s * 8 + hl);
                acc_half8(acc, a);
            }
            // merge the 4 edge groups (off the per-edge critical path)
#pragma unroll
            for (int d = 0; d < 8; d++) {
                acc[d] += __shfl_xor_sync(0xffffffffu, acc[d], 8);
                acc[d] += __shfl_xor_sync(0xffffffffu, acc[d], 16);
            }
            if (qw == 0) {
                float iv = __ldg(g_inv + n);
                float4* vp = reinterpret_cast<float4*>(vsm + (r0 + r) * D + 8 * hl);
                vp[0] = make_float4(acc[0] * iv, acc[1] * iv, acc[2] * iv, acc[3] * iv);
                vp[1] = make_float4(acc[4] * iv, acc[5] * iv, acc[6] * iv, acc[7] * iv);
            }
        }
        __syncwarp();                     // vsm slice is warp-private

        // ---- FFMA2 GEMM: out[tile rows, :] = vsm @ W + b ----
        ull acc_a[8], acc_b[8];
#pragma unroll
        for (int r = 0; r < 8; r++) { acc_a[r] = 0ull; acc_b[r] = 0ull; }

#pragma unroll
        for (int k4 = 0; k4 < 16; k4++) {
            float4 wav = wa4[k4];
            float4 wbv = wb4[k4];
            ull wa0 = reinterpret_cast<const ull*>(&wav)[0];
            ull wa1 = reinterpret_cast<const ull*>(&wav)[1];
            ull wb0 = reinterpret_cast<const ull*>(&wbv)[0];
            ull wb1 = reinterpret_cast<const ull*>(&wbv)[1];
#pragma unroll
            for (int r = 0; r < 8; r++) {
                float4 v = *reinterpret_cast<const float4*>(vsm + (r0 + r) * D + k4 * 4);
                ull v0 = reinterpret_cast<const ull*>(&v)[0];
                ull v1 = reinterpret_cast<const ull*>(&v)[1];
                ffma2(acc_a[r], v0, wa0);
                ffma2(acc_a[r], v1, wa1);
                ffma2(acc_b[r], v0, wb0);
                ffma2(acc_b[r], v1, wb1);
            }
        }

#pragma unroll
        for (int r = 0; r < 8; r++) {
            int row = rowBase + r;
            if (row < N_NODES) {
                float2 pa = *reinterpret_cast<float2*>(&acc_a[r]);
                float2 pb = *reinterpret_cast<float2*>(&acc_b[r]);
                float o0 = pa.x + pa.y + bias0;
                float o1 = pb.x + pb.y + bias1;
                if (RELU) { o0 = fmaxf(o0, 0.f); o1 = fmaxf(o1, 0.f); }
                if (OUTF) {
                    outf[(size_t)row * D + lane]      = o0;
                    outf[(size_t)row * D + lane + 32] = o1;
                } else {
                    __half* oh = reinterpret_cast<__half*>(outh) + (size_t)row * D;
                    oh[lane]      = __float2half_rn(o0);
                    oh[lane + 32] = __float2half_rn(o1);
                }
            }
        }
        __syncwarp();                     // done with vsm slice before reuse
    }
}

// ---------------------------------------------------------------------------
extern "C" void kernel_launch(void* const* d_in, const int* in_sizes, int n_in,
                              void* d_out, int out_size) {
    const float* x   = (const float*)d_in[0];
    const int*   src = (const int*)  d_in[1];
    const int*   dst = (const int*)  d_in[2];
    const float* W0  = (const float*)d_in[3];
    const float* b0  = (const float*)d_in[4];
    const float* W1  = (const float*)d_in[5];
    const float* b1  = (const float*)d_in[6];
    const float* W2  = (const float*)d_in[7];
    const float* b2  = (const float*)d_in[8];
    float* out = (float*)d_out;

    __half2* hx; cudaGetSymbolAddress((void**)&hx, g_hx);
    __half2* h1; cudaGetSymbolAddress((void**)&h1, g_h1);
    __half2* h2; cudaGetSymbolAddress((void**)&h2, g_h2);

    const int edge_grid = (N_EDGES + 255) / 256;
    const int cc_grid   = (N_NODES * (D / 2) + 255) / 256;   // covers cvt+count

    // CSR build (fused cvt+count -> per-block scan -> fused finalize -> fill)
    cvt_count_kernel<<<cc_grid, 256>>>(x, dst);
    scanA_kernel<<<SCAN_GRID, SCAN_B>>>();
    scanC_kernel<<<SCAN_GRID, SCAN_B>>>();
    fill_kernel<<<edge_grid, 256>>>(src, dst);

    layer_kernel<true,  false, 0><<<LAYER_GRID, 256>>>(hx, W0, b0, nullptr, h1);
    layer_kernel<true,  false, 1><<<LAYER_GRID, 256>>>(h1, W1, b1, nullptr, h2);
    layer_kernel<false, true,  2><<<LAYER_GRID, 256>>>(h2, W2, b2, out, nullptr);
}